// round 2
// baseline (speedup 1.0000x reference)
#include <cuda_runtime.h>
#include <cuda_bf16.h>
#include <math.h>

#define MT 4096      // B*T
#define CC 1024      // C
#define NH 16
#define HD 64

// ---------------- scratch (static device arrays; no allocations) ----------------
__device__ float g_sx  [MT*CC];
__device__ float g_xmix[MT*CC];
__device__ float g_P   [MT*160];
__device__ float g_wx  [MT*CC];
__device__ float g_kx  [MT*CC];
__device__ float g_vx  [MT*CC];
__device__ float g_rx  [MT*CC];
__device__ float g_gx  [MT*CC];
__device__ float g_rr  [MT*CC];
__device__ float g_kk  [MT*CC];
__device__ float g_vv  [MT*CC];
__device__ float g_gg  [MT*CC];
__device__ float g_t1  [MT*64];
__device__ float g_wd  [MT*CC];
__device__ float g_og  [MT*CC];

// Device-side scratch resolver — avoids any host-side symbol-address API.
__device__ __forceinline__ float* dbuf(int id) {
    switch (id) {
        case 0:  return g_sx;
        case 1:  return g_xmix;
        case 2:  return g_P;
        case 3:  return g_wx;
        case 4:  return g_kx;
        case 5:  return g_vx;
        case 6:  return g_rx;
        case 7:  return g_gx;
        case 8:  return g_rr;
        case 9:  return g_kk;
        case 10: return g_vv;
        case 11: return g_gg;
        case 12: return g_t1;
        case 13: return g_wd;
        default: return g_og;  // 14
    }
}

// ---------------- prep: sx = x_{t-1} - x_t ; xmix = x + sx*x_maa ----------------
__global__ void prep_kernel(const float* __restrict__ x, const float* __restrict__ x_maa) {
    int idx = (blockIdx.x * 256 + threadIdx.x) * 4;
    if (idx >= MT * CC) return;
    int row = idx / CC;
    int col = idx % CC;
    int t = row & 1023;
    float4 xc = *(const float4*)(x + idx);
    float4 xp;
    if (t == 0) xp = make_float4(0.f, 0.f, 0.f, 0.f);
    else        xp = *(const float4*)(x + idx - CC);
    float4 ma = *(const float4*)(x_maa + col);
    float4 s, m;
    s.x = xp.x - xc.x; s.y = xp.y - xc.y; s.z = xp.z - xc.z; s.w = xp.w - xc.w;
    m.x = fmaf(s.x, ma.x, xc.x); m.y = fmaf(s.y, ma.y, xc.y);
    m.z = fmaf(s.z, ma.z, xc.z); m.w = fmaf(s.w, ma.w, xc.w);
    *(float4*)(g_sx + idx)   = s;
    *(float4*)(g_xmix + idx) = m;
}

// ---------------- generic guarded SGEMM (small shapes), with epilogue ----------------
// EPI: 0=store 1=tanh
template<int EPI>
__global__ void gemm_generic(int a_id, const float* __restrict__ B,
                             int c_id, int M, int N, int K) {
    const float* A = dbuf(a_id);
    float* C = dbuf(c_id);
    const int BM = 64, BN = 64, BK = 16, TM = 4, TN = 4;
    __shared__ float As[BK][BM];
    __shared__ float Bs[BK][BN + 1];
    int tid = threadIdx.x;
    int bm = blockIdx.y * BM, bn = blockIdx.x * BN;
    int tcol = (tid % 16) * TN, trow = (tid / 16) * TM;
    float acc[TM][TN] = {};
    for (int k0 = 0; k0 < K; k0 += BK) {
        for (int i = tid; i < BM * BK; i += 256) {
            int r = i / BK, c = i % BK;
            int gr = bm + r, gc = k0 + c;
            float v = 0.f;
            if (gr < M && gc < K) v = A[(size_t)gr * K + gc];
            As[c][r] = v;
        }
        for (int i = tid; i < BK * BN; i += 256) {
            int r = i / BN, c = i % BN;
            int gr = k0 + r, gc = bn + c;
            float v = 0.f;
            if (gr < K && gc < N) v = B[(size_t)gr * N + gc];
            Bs[r][c] = v;
        }
        __syncthreads();
#pragma unroll
        for (int kk = 0; kk < BK; ++kk) {
            float ra[TM], rb[TN];
#pragma unroll
            for (int i = 0; i < TM; ++i) ra[i] = As[kk][trow + i];
#pragma unroll
            for (int j = 0; j < TN; ++j) rb[j] = Bs[kk][tcol + j];
#pragma unroll
            for (int i = 0; i < TM; ++i)
#pragma unroll
                for (int j = 0; j < TN; ++j)
                    acc[i][j] = fmaf(ra[i], rb[j], acc[i][j]);
        }
        __syncthreads();
    }
#pragma unroll
    for (int i = 0; i < TM; ++i) {
        int gr = bm + trow + i;
        if (gr >= M) continue;
#pragma unroll
        for (int j = 0; j < TN; ++j) {
            int gc = bn + tcol + j;
            if (gc >= N) continue;
            float v = acc[i][j];
            if (EPI == 1) v = tanhf(v);
            C[(size_t)gr * N + gc] = v;
        }
    }
}

// ---------------- fast 128x128x8 double-buffered SGEMM (M,N mult of 128, K mult of 8) ----------------
// EPI: 0=store 2=silu 3=exp(-exp(extra[col]+v))
template<int EPI>
__global__ void __launch_bounds__(256)
sgemm128(int a_id, const float* __restrict__ B,
         float* __restrict__ C_ext, int c_id, int M, int N, int K,
         const float* __restrict__ extra) {
    const float* A = dbuf(a_id);
    float* C = (c_id < 0) ? C_ext : dbuf(c_id);
    __shared__ float As[2][8][128];
    __shared__ float Bs[2][8][128];
    int tid = threadIdx.x;
    int bm = blockIdx.y * 128, bn = blockIdx.x * 128;
    int arow = tid >> 1,  acol = (tid & 1) * 4;
    int brow = tid >> 5,  bcol = (tid & 31) * 4;
    const float* Ap = A + (size_t)(bm + arow) * K + acol;
    const float* Bp = B + (size_t)brow * N + bn + bcol;
    int tx = (tid & 15) * 8, ty = (tid >> 4) * 8;
    float acc[8][8] = {};

    float4 a4 = *(const float4*)Ap;
    float4 b4 = *(const float4*)Bp;
    As[0][acol + 0][arow] = a4.x; As[0][acol + 1][arow] = a4.y;
    As[0][acol + 2][arow] = a4.z; As[0][acol + 3][arow] = a4.w;
    *(float4*)&Bs[0][brow][bcol] = b4;
    __syncthreads();

    int nk = K >> 3;
    for (int kt = 0; kt < nk; ++kt) {
        int cur = kt & 1;
        bool more = (kt + 1 < nk);
        float4 a4n, b4n;
        if (more) {
            a4n = *(const float4*)(Ap + (size_t)(kt + 1) * 8);
            b4n = *(const float4*)(Bp + (size_t)(kt + 1) * 8 * N);
        }
#pragma unroll
        for (int kk = 0; kk < 8; ++kk) {
            float ra[8], rb[8];
#pragma unroll
            for (int i = 0; i < 8; ++i) { ra[i] = As[cur][kk][ty + i]; rb[i] = Bs[cur][kk][tx + i]; }
#pragma unroll
            for (int i = 0; i < 8; ++i)
#pragma unroll
                for (int j = 0; j < 8; ++j)
                    acc[i][j] = fmaf(ra[i], rb[j], acc[i][j]);
        }
        if (more) {
            int nxt = cur ^ 1;
            As[nxt][acol + 0][arow] = a4n.x; As[nxt][acol + 1][arow] = a4n.y;
            As[nxt][acol + 2][arow] = a4n.z; As[nxt][acol + 3][arow] = a4n.w;
            *(float4*)&Bs[nxt][brow][bcol] = b4n;
            __syncthreads();
        }
    }

#pragma unroll
    for (int i = 0; i < 8; ++i) {
        size_t rowoff = (size_t)(bm + ty + i) * N;
#pragma unroll
        for (int j = 0; j < 8; j += 4) {
            float4 v;
            float vv[4] = { acc[i][j], acc[i][j + 1], acc[i][j + 2], acc[i][j + 3] };
#pragma unroll
            for (int q = 0; q < 4; ++q) {
                float t = vv[q];
                if (EPI == 2) { float sg = 1.f / (1.f + expf(-t)); t = t * sg; }
                else if (EPI == 3) { t = expf(-expf(extra[bn + tx + j + q] + t)); }
                vv[q] = t;
            }
            v.x = vv[0]; v.y = vv[1]; v.z = vv[2]; v.w = vv[3];
            *(float4*)(C + rowoff + bn + tx + j) = v;
        }
    }
}

// ---------------- fused K=32 mix GEMM + apply: out = x + sx*(maa + P_f @ W2_f) ----------------
__global__ void __launch_bounds__(256)
mix_kernel(const float* __restrict__ x,
           const float* __restrict__ w_maa, const float* __restrict__ k_maa,
           const float* __restrict__ v_maa, const float* __restrict__ r_maa,
           const float* __restrict__ gm_maa,
           const float* __restrict__ tm_w2) {
    int f = blockIdx.z;
    int bm = blockIdx.y * 128, bn = blockIdx.x * 128;
    __shared__ float Ps[128][33];
    __shared__ float Ws[32][128];
    int tid = threadIdx.x;
    // load P tile: rows bm..bm+127, cols f*32..f*32+31 (row stride 160)
    for (int i = tid; i < 128 * 8; i += 256) {
        int r = i >> 3, c4 = (i & 7) * 4;
        float4 p4 = *(const float4*)(g_P + (size_t)(bm + r) * 160 + f * 32 + c4);
        Ps[r][c4] = p4.x; Ps[r][c4 + 1] = p4.y; Ps[r][c4 + 2] = p4.z; Ps[r][c4 + 3] = p4.w;
    }
    for (int i = tid; i < 32 * 32; i += 256) {
        int r = i >> 5, c4 = (i & 31) * 4;
        *(float4*)&Ws[r][c4] = *(const float4*)(tm_w2 + ((size_t)f * 32 + r) * 1024 + bn + c4);
    }
    __syncthreads();
    int tx = (tid & 15) * 8, ty = (tid >> 4) * 8;
    float acc[8][8] = {};
#pragma unroll
    for (int kk = 0; kk < 32; ++kk) {
        float ra[8], rb[8];
#pragma unroll
        for (int i = 0; i < 8; ++i) { ra[i] = Ps[ty + i][kk]; rb[i] = Ws[kk][tx + i]; }
#pragma unroll
        for (int i = 0; i < 8; ++i)
#pragma unroll
            for (int j = 0; j < 8; ++j)
                acc[i][j] = fmaf(ra[i], rb[j], acc[i][j]);
    }
    const float* maa = (f == 0) ? w_maa : (f == 1) ? k_maa : (f == 2) ? v_maa : (f == 3) ? r_maa : gm_maa;
    float* out = (f == 0) ? g_wx : (f == 1) ? g_kx : (f == 2) ? g_vx : (f == 3) ? g_rx : g_gx;
#pragma unroll
    for (int i = 0; i < 8; ++i) {
        size_t rowoff = (size_t)(bm + ty + i) * 1024;
#pragma unroll
        for (int j = 0; j < 8; ++j) {
            int gc = bn + tx + j;
            float m = acc[i][j];
            out[rowoff + gc] = fmaf(g_sx[rowoff + gc], maa[gc] + m, x[rowoff + gc]);
        }
    }
}

// ---------------- WKV recurrence + /8 + GroupNorm(per head) + *g ; writes g_og ----------------
__global__ void __launch_bounds__(256)
wkv_kernel(const float* __restrict__ u,
           const float* __restrict__ lnw, const float* __restrict__ lnb) {
    const float* r = g_rr;
    const float* k = g_kk;
    const float* v = g_vv;
    const float* w = g_wd;
    const float* g = g_gg;
    int b = blockIdx.x >> 4, h = blockIdx.x & 15;
    int tid = threadIdx.x;
    int j = tid & 63, q = tid >> 6;    // thread owns column j, state rows q*16..q*16+15
    __shared__ float skk[64], srr[64], sww[64];
    __shared__ float ypart[256];
    float s[16];
#pragma unroll
    for (int i = 0; i < 16; ++i) s[i] = 0.f;
    float uq[16];
#pragma unroll
    for (int i = 0; i < 16; ++i) uq[i] = u[h * 64 + q * 16 + i];
    size_t base = (size_t)b * 1024 * 1024 + h * 64;
    float lwa = 0.f, lwb = 0.f, lba = 0.f, lbb = 0.f;
    if (tid < 32) {
        lwa = lnw[h * 64 + tid];      lwb = lnw[h * 64 + tid + 32];
        lba = lnb[h * 64 + tid];      lbb = lnb[h * 64 + tid + 32];
    }
    for (int t = 0; t < 1024; ++t) {
        size_t off = base + (size_t)t * 1024;
        if (tid < 64)       skk[tid]       = k[off + tid];
        else if (tid < 128) srr[tid - 64]  = r[off + tid - 64];
        else if (tid < 192) sww[tid - 128] = w[off + tid - 128];
        float vj = v[off + j];
        __syncthreads();
        float y = 0.f;
#pragma unroll
        for (int i = 0; i < 16; ++i) {
            int ii = q * 16 + i;
            float kv = skk[ii] * vj;
            y = fmaf(srr[ii], fmaf(uq[i], kv, s[i]), y);
            s[i] = fmaf(sww[ii], s[i], kv);
        }
        ypart[tid] = y;
        __syncthreads();
        if (tid < 32) {
            float ya = (ypart[tid]      + ypart[tid + 64]  + ypart[tid + 128] + ypart[tid + 192]) * 0.125f;
            float yb = (ypart[tid + 32] + ypart[tid + 96]  + ypart[tid + 160] + ypart[tid + 224]) * 0.125f;
            float sm = ya + yb, sq = ya * ya + yb * yb;
#pragma unroll
            for (int o = 16; o; o >>= 1) {
                sm += __shfl_xor_sync(0xffffffffu, sm, o);
                sq += __shfl_xor_sync(0xffffffffu, sq, o);
            }
            float mu  = sm * (1.f / 64.f);
            float var = sq * (1.f / 64.f) - mu * mu;
            float inv = rsqrtf(var + 1e-5f);
            float oa = (ya - mu) * inv * lwa + lba;
            float ob = (yb - mu) * inv * lwb + lbb;
            g_og[off + tid]      = oa * g[off + tid];
            g_og[off + tid + 32] = ob * g[off + tid + 32];
        }
        __syncthreads();
    }
}

// ---------------- launch ----------------
extern "C" void kernel_launch(void* const* d_in, const int* in_sizes, int n_in,
                              void* d_out, int out_size) {
    const float* x          = (const float*)d_in[0];
    const float* x_maa      = (const float*)d_in[1];
    const float* w_maa      = (const float*)d_in[2];
    const float* k_maa      = (const float*)d_in[3];
    const float* v_maa      = (const float*)d_in[4];
    const float* r_maa      = (const float*)d_in[5];
    const float* gm_maa     = (const float*)d_in[6];
    const float* tm_w1      = (const float*)d_in[7];
    const float* tm_w2      = (const float*)d_in[8];
    const float* td_w1      = (const float*)d_in[9];
    const float* td_w2      = (const float*)d_in[10];
    const float* time_decay = (const float*)d_in[11];
    const float* time_first = (const float*)d_in[12];
    const float* Wr         = (const float*)d_in[13];
    const float* Wk         = (const float*)d_in[14];
    const float* Wv         = (const float*)d_in[15];
    const float* Wg         = (const float*)d_in[16];
    const float* Wo         = (const float*)d_in[17];
    const float* ln_w       = (const float*)d_in[18];
    const float* ln_b       = (const float*)d_in[19];
    float* out = (float*)d_out;

    // buffer ids: 0 sx, 1 xmix, 2 P, 3 wx, 4 kx, 5 vx, 6 rx, 7 gx,
    //             8 rr, 9 kk, 10 vv, 11 gg, 12 t1, 13 wd, 14 og

    // 1) token shift + xmix
    prep_kernel<<<(MT * CC / 4 + 255) / 256, 256>>>(x, x_maa);

    // 2) P = tanh(xmix @ tm_w1)   [4096,160]
    gemm_generic<1><<<dim3(3, 64), 256>>>(1, tm_w1, 2, MT, 160, CC);

    // 3) five mixed inputs wx/kx/vx/rx/gx (K=32 GEMM fused with apply)
    mix_kernel<<<dim3(8, 32, 5), 256>>>(x, w_maa, k_maa, v_maa, r_maa, gm_maa, tm_w2);

    // 4) big projections
    sgemm128<0><<<dim3(8, 32), 256>>>(6, Wr, nullptr, 8,  MT, CC, CC, nullptr);
    sgemm128<0><<<dim3(8, 32), 256>>>(4, Wk, nullptr, 9,  MT, CC, CC, nullptr);
    sgemm128<0><<<dim3(8, 32), 256>>>(5, Wv, nullptr, 10, MT, CC, CC, nullptr);
    sgemm128<2><<<dim3(8, 32), 256>>>(7, Wg, nullptr, 11, MT, CC, CC, nullptr);   // silu

    // 5) decay path: t1 = tanh(wx @ td_w1) [4096,64]; wd = exp(-exp(td + t1 @ td_w2))
    gemm_generic<1><<<dim3(1, 64), 256>>>(3, td_w1, 12, MT, 64, CC);
    sgemm128<3><<<dim3(8, 32), 256>>>(12, td_w2, nullptr, 13, MT, CC, 64, time_decay);

    // 6) WKV recurrence + groupnorm + gate
    wkv_kernel<<<64, 256>>>(time_first, ln_w, ln_b);

    // 7) output projection
    sgemm128<0><<<dim3(8, 32), 256>>>(14, Wo, out, -1, MT, CC, CC, nullptr);
}

// round 3
// speedup vs baseline: 1.8266x; 1.8266x over previous
#include <cuda_runtime.h>
#include <cuda_bf16.h>
#include <math.h>

#define MT 4096      // B*T
#define CC 1024      // C
#define NH 16
#define HD 64
#define NC 16        // WKV chunks
#define CL 64        // chunk length (NC*CL = 1024 = T)

// ---------------- scratch (static device arrays; no allocations) ----------------
__device__ float g_sx  [MT*CC];   // sx; later reused as S0 (chunk initial states, 16MB)
__device__ float g_xmix[MT*CC];   // xmix; later reused as S (chunk local end states, 16MB)
__device__ float g_P   [MT*160];
__device__ float g_wx  [MT*CC];
__device__ float g_kx  [MT*CC];
__device__ float g_vx  [MT*CC];
__device__ float g_rx  [MT*CC];
__device__ float g_gx  [MT*CC];
__device__ float g_rr  [MT*CC];
__device__ float g_kk  [MT*CC];
__device__ float g_vv  [MT*CC];
__device__ float g_gg  [MT*CC];
__device__ float g_t1  [MT*64];   // t1; later reused as prodW (64K floats)
__device__ float g_wd  [MT*CC];
__device__ float g_og  [MT*CC];

__device__ __forceinline__ float* dbuf(int id) {
    switch (id) {
        case 0:  return g_sx;
        case 1:  return g_xmix;
        case 2:  return g_P;
        case 3:  return g_wx;
        case 4:  return g_kx;
        case 5:  return g_vx;
        case 6:  return g_rx;
        case 7:  return g_gx;
        case 8:  return g_rr;
        case 9:  return g_kk;
        case 10: return g_vv;
        case 11: return g_gg;
        case 12: return g_t1;
        case 13: return g_wd;
        default: return g_og;  // 14
    }
}

// ---------------- prep: sx = x_{t-1} - x_t ; xmix = x + sx*x_maa ----------------
__global__ void prep_kernel(const float* __restrict__ x, const float* __restrict__ x_maa) {
    int idx = (blockIdx.x * 256 + threadIdx.x) * 4;
    if (idx >= MT * CC) return;
    int row = idx / CC;
    int col = idx % CC;
    int t = row & 1023;
    float4 xc = *(const float4*)(x + idx);
    float4 xp;
    if (t == 0) xp = make_float4(0.f, 0.f, 0.f, 0.f);
    else        xp = *(const float4*)(x + idx - CC);
    float4 ma = *(const float4*)(x_maa + col);
    float4 s, m;
    s.x = xp.x - xc.x; s.y = xp.y - xc.y; s.z = xp.z - xc.z; s.w = xp.w - xc.w;
    m.x = fmaf(s.x, ma.x, xc.x); m.y = fmaf(s.y, ma.y, xc.y);
    m.z = fmaf(s.z, ma.z, xc.z); m.w = fmaf(s.w, ma.w, xc.w);
    *(float4*)(g_sx + idx)   = s;
    *(float4*)(g_xmix + idx) = m;
}

// ---------------- generic guarded SGEMM (small shapes), with epilogue ----------------
// EPI: 0=store 1=tanh
template<int EPI>
__global__ void gemm_generic(int a_id, const float* __restrict__ B,
                             int c_id, int M, int N, int K) {
    const float* A = dbuf(a_id);
    float* C = dbuf(c_id);
    const int BM = 64, BN = 64, BK = 16, TM = 4, TN = 4;
    __shared__ float As[BK][BM];
    __shared__ float Bs[BK][BN + 1];
    int tid = threadIdx.x;
    int bm = blockIdx.y * BM, bn = blockIdx.x * BN;
    int tcol = (tid % 16) * TN, trow = (tid / 16) * TM;
    float acc[TM][TN] = {};
    for (int k0 = 0; k0 < K; k0 += BK) {
        for (int i = tid; i < BM * BK; i += 256) {
            int r = i / BK, c = i % BK;
            int gr = bm + r, gc = k0 + c;
            float v = 0.f;
            if (gr < M && gc < K) v = A[(size_t)gr * K + gc];
            As[c][r] = v;
        }
        for (int i = tid; i < BK * BN; i += 256) {
            int r = i / BN, c = i % BN;
            int gr = k0 + r, gc = bn + c;
            float v = 0.f;
            if (gr < K && gc < N) v = B[(size_t)gr * N + gc];
            Bs[r][c] = v;
        }
        __syncthreads();
#pragma unroll
        for (int kk = 0; kk < BK; ++kk) {
            float ra[TM], rb[TN];
#pragma unroll
            for (int i = 0; i < TM; ++i) ra[i] = As[kk][trow + i];
#pragma unroll
            for (int j = 0; j < TN; ++j) rb[j] = Bs[kk][tcol + j];
#pragma unroll
            for (int i = 0; i < TM; ++i)
#pragma unroll
                for (int j = 0; j < TN; ++j)
                    acc[i][j] = fmaf(ra[i], rb[j], acc[i][j]);
        }
        __syncthreads();
    }
#pragma unroll
    for (int i = 0; i < TM; ++i) {
        int gr = bm + trow + i;
        if (gr >= M) continue;
#pragma unroll
        for (int j = 0; j < TN; ++j) {
            int gc = bn + tcol + j;
            if (gc >= N) continue;
            float v = acc[i][j];
            if (EPI == 1) v = tanhf(v);
            C[(size_t)gr * N + gc] = v;
        }
    }
}

// ---------------- fast 128x128x8 double-buffered SGEMM ----------------
// EPI: 0=store 3=exp(-exp(extra[col]+v))
template<int EPI>
__global__ void __launch_bounds__(256)
sgemm128(int a_id, const float* __restrict__ B,
         float* __restrict__ C_ext, int c_id, int M, int N, int K,
         const float* __restrict__ extra) {
    const float* A = dbuf(a_id);
    float* C = (c_id < 0) ? C_ext : dbuf(c_id);
    __shared__ float As[2][8][128];
    __shared__ float Bs[2][8][128];
    int tid = threadIdx.x;
    int bm = blockIdx.y * 128, bn = blockIdx.x * 128;
    int arow = tid >> 1,  acol = (tid & 1) * 4;
    int brow = tid >> 5,  bcol = (tid & 31) * 4;
    const float* Ap = A + (size_t)(bm + arow) * K + acol;
    const float* Bp = B + (size_t)brow * N + bn + bcol;
    int tx = (tid & 15) * 8, ty = (tid >> 4) * 8;
    float acc[8][8] = {};

    float4 a4 = *(const float4*)Ap;
    float4 b4 = *(const float4*)Bp;
    As[0][acol + 0][arow] = a4.x; As[0][acol + 1][arow] = a4.y;
    As[0][acol + 2][arow] = a4.z; As[0][acol + 3][arow] = a4.w;
    *(float4*)&Bs[0][brow][bcol] = b4;
    __syncthreads();

    int nk = K >> 3;
    for (int kt = 0; kt < nk; ++kt) {
        int cur = kt & 1;
        bool more = (kt + 1 < nk);
        float4 a4n, b4n;
        if (more) {
            a4n = *(const float4*)(Ap + (size_t)(kt + 1) * 8);
            b4n = *(const float4*)(Bp + (size_t)(kt + 1) * 8 * N);
        }
#pragma unroll
        for (int kk = 0; kk < 8; ++kk) {
            float ra[8], rb[8];
#pragma unroll
            for (int i = 0; i < 8; ++i) { ra[i] = As[cur][kk][ty + i]; rb[i] = Bs[cur][kk][tx + i]; }
#pragma unroll
            for (int i = 0; i < 8; ++i)
#pragma unroll
                for (int j = 0; j < 8; ++j)
                    acc[i][j] = fmaf(ra[i], rb[j], acc[i][j]);
        }
        if (more) {
            int nxt = cur ^ 1;
            As[nxt][acol + 0][arow] = a4n.x; As[nxt][acol + 1][arow] = a4n.y;
            As[nxt][acol + 2][arow] = a4n.z; As[nxt][acol + 3][arow] = a4n.w;
            *(float4*)&Bs[nxt][brow][bcol] = b4n;
            __syncthreads();
        }
    }

#pragma unroll
    for (int i = 0; i < 8; ++i) {
        size_t rowoff = (size_t)(bm + ty + i) * N;
#pragma unroll
        for (int j = 0; j < 8; j += 4) {
            float4 v;
            float vv[4] = { acc[i][j], acc[i][j + 1], acc[i][j + 2], acc[i][j + 3] };
#pragma unroll
            for (int q = 0; q < 4; ++q) {
                float t = vv[q];
                if (EPI == 3) { t = expf(-expf(extra[bn + tx + j + q] + t)); }
                vv[q] = t;
            }
            v.x = vv[0]; v.y = vv[1]; v.z = vv[2]; v.w = vv[3];
            *(float4*)(C + rowoff + bn + tx + j) = v;
        }
    }
}

// ---------------- batched 4-way projection GEMM (r/k/v/g), z selects ----------------
__global__ void __launch_bounds__(256)
proj4_kernel(const float* __restrict__ Wr, const float* __restrict__ Wk,
             const float* __restrict__ Wv, const float* __restrict__ Wg) {
    int z = blockIdx.z;
    const float* A = (z == 0) ? g_rx : (z == 1) ? g_kx : (z == 2) ? g_vx : g_gx;
    const float* B = (z == 0) ? Wr : (z == 1) ? Wk : (z == 2) ? Wv : Wg;
    float* C       = (z == 0) ? g_rr : (z == 1) ? g_kk : (z == 2) ? g_vv : g_gg;
    const int N = CC, K = CC;
    __shared__ float As[2][8][128];
    __shared__ float Bs[2][8][128];
    int tid = threadIdx.x;
    int bm = blockIdx.y * 128, bn = blockIdx.x * 128;
    int arow = tid >> 1,  acol = (tid & 1) * 4;
    int brow = tid >> 5,  bcol = (tid & 31) * 4;
    const float* Ap = A + (size_t)(bm + arow) * K + acol;
    const float* Bp = B + (size_t)brow * N + bn + bcol;
    int tx = (tid & 15) * 8, ty = (tid >> 4) * 8;
    float acc[8][8] = {};

    float4 a4 = *(const float4*)Ap;
    float4 b4 = *(const float4*)Bp;
    As[0][acol + 0][arow] = a4.x; As[0][acol + 1][arow] = a4.y;
    As[0][acol + 2][arow] = a4.z; As[0][acol + 3][arow] = a4.w;
    *(float4*)&Bs[0][brow][bcol] = b4;
    __syncthreads();

    const int nk = K >> 3;
    for (int kt = 0; kt < nk; ++kt) {
        int cur = kt & 1;
        bool more = (kt + 1 < nk);
        float4 a4n, b4n;
        if (more) {
            a4n = *(const float4*)(Ap + (size_t)(kt + 1) * 8);
            b4n = *(const float4*)(Bp + (size_t)(kt + 1) * 8 * N);
        }
#pragma unroll
        for (int kk = 0; kk < 8; ++kk) {
            float ra[8], rb[8];
#pragma unroll
            for (int i = 0; i < 8; ++i) { ra[i] = As[cur][kk][ty + i]; rb[i] = Bs[cur][kk][tx + i]; }
#pragma unroll
            for (int i = 0; i < 8; ++i)
#pragma unroll
                for (int j = 0; j < 8; ++j)
                    acc[i][j] = fmaf(ra[i], rb[j], acc[i][j]);
        }
        if (more) {
            int nxt = cur ^ 1;
            As[nxt][acol + 0][arow] = a4n.x; As[nxt][acol + 1][arow] = a4n.y;
            As[nxt][acol + 2][arow] = a4n.z; As[nxt][acol + 3][arow] = a4n.w;
            *(float4*)&Bs[nxt][brow][bcol] = b4n;
            __syncthreads();
        }
    }

    bool silu = (z == 3);
#pragma unroll
    for (int i = 0; i < 8; ++i) {
        size_t rowoff = (size_t)(bm + ty + i) * N;
#pragma unroll
        for (int j = 0; j < 8; j += 4) {
            float vv[4] = { acc[i][j], acc[i][j + 1], acc[i][j + 2], acc[i][j + 3] };
            if (silu) {
#pragma unroll
                for (int q = 0; q < 4; ++q) {
                    float t = vv[q];
                    float sg = 1.f / (1.f + expf(-t));
                    vv[q] = t * sg;
                }
            }
            float4 v;
            v.x = vv[0]; v.y = vv[1]; v.z = vv[2]; v.w = vv[3];
            *(float4*)(C + rowoff + bn + tx + j) = v;
        }
    }
}

// ---------------- fused K=32 mix GEMM + apply: out = x + sx*(maa + P_f @ W2_f) ----------------
__global__ void __launch_bounds__(256)
mix_kernel(const float* __restrict__ x,
           const float* __restrict__ w_maa, const float* __restrict__ k_maa,
           const float* __restrict__ v_maa, const float* __restrict__ r_maa,
           const float* __restrict__ gm_maa,
           const float* __restrict__ tm_w2) {
    int f = blockIdx.z;
    int bm = blockIdx.y * 128, bn = blockIdx.x * 128;
    __shared__ float Ps[128][33];
    __shared__ float Ws[32][128];
    int tid = threadIdx.x;
    for (int i = tid; i < 128 * 8; i += 256) {
        int r = i >> 3, c4 = (i & 7) * 4;
        float4 p4 = *(const float4*)(g_P + (size_t)(bm + r) * 160 + f * 32 + c4);
        Ps[r][c4] = p4.x; Ps[r][c4 + 1] = p4.y; Ps[r][c4 + 2] = p4.z; Ps[r][c4 + 3] = p4.w;
    }
    for (int i = tid; i < 32 * 32; i += 256) {
        int r = i >> 5, c4 = (i & 31) * 4;
        *(float4*)&Ws[r][c4] = *(const float4*)(tm_w2 + ((size_t)f * 32 + r) * 1024 + bn + c4);
    }
    __syncthreads();
    int tx = (tid & 15) * 8, ty = (tid >> 4) * 8;
    float acc[8][8] = {};
#pragma unroll
    for (int kk = 0; kk < 32; ++kk) {
        float ra[8], rb[8];
#pragma unroll
        for (int i = 0; i < 8; ++i) { ra[i] = Ps[ty + i][kk]; rb[i] = Ws[kk][tx + i]; }
#pragma unroll
        for (int i = 0; i < 8; ++i)
#pragma unroll
            for (int j = 0; j < 8; ++j)
                acc[i][j] = fmaf(ra[i], rb[j], acc[i][j]);
    }
    const float* maa = (f == 0) ? w_maa : (f == 1) ? k_maa : (f == 2) ? v_maa : (f == 3) ? r_maa : gm_maa;
    float* out = (f == 0) ? g_wx : (f == 1) ? g_kx : (f == 2) ? g_vx : (f == 3) ? g_rx : g_gx;
#pragma unroll
    for (int i = 0; i < 8; ++i) {
        size_t rowoff = (size_t)(bm + ty + i) * 1024;
#pragma unroll
        for (int j = 0; j < 8; ++j) {
            int gc = bn + tx + j;
            float m = acc[i][j];
            out[rowoff + gc] = fmaf(g_sx[rowoff + gc], maa[gc] + m, x[rowoff + gc]);
        }
    }
}

// ================= WKV: chunked parallel scan, barrier-free warps =================
// Warp unit: (bh, chunk, col-half). 2048 warps. Lane owns column j, full 64-row state in regs.
// S (local end states) -> g_xmix ; S0 (initial states) -> g_sx ; prodW -> g_t1.
// Layout: S/S0 idx = bh*65536 + c*4096 + i*64 + j ; prodW idx = bh*1024 + c*64 + i.

// Pass A: from zero state, compute chunk-local end state + per-row decay product.
__global__ void __launch_bounds__(256)
wkv_passA() {
    int wid  = blockIdx.x * 8 + (threadIdx.x >> 5);
    int lane = threadIdx.x & 31;
    int half = wid & 1, c = (wid >> 1) & (NC - 1), bh = wid >> 5;
    int b = bh >> 4, h = bh & 15;
    int j = half * 32 + lane;
    size_t base = (size_t)b * 1048576 + h * 64;
    float s[64];
#pragma unroll
    for (int i = 0; i < 64; ++i) s[i] = 0.f;
    float pw0 = 1.f, pw1 = 1.f;
    int t0 = c * CL;
    for (int t = 0; t < CL; ++t) {
        size_t off = base + (size_t)(t0 + t) * 1024;
        float k0 = g_kk[off + lane], k1 = g_kk[off + lane + 32];
        float w0 = g_wd[off + lane], w1 = g_wd[off + lane + 32];
        float vj = g_vv[off + j];
        pw0 *= w0; pw1 *= w1;
#pragma unroll
        for (int i = 0; i < 32; ++i) {
            float ki = __shfl_sync(0xffffffffu, k0, i);
            float wi = __shfl_sync(0xffffffffu, w0, i);
            s[i] = fmaf(wi, s[i], ki * vj);
        }
#pragma unroll
        for (int i = 0; i < 32; ++i) {
            float ki = __shfl_sync(0xffffffffu, k1, i);
            float wi = __shfl_sync(0xffffffffu, w1, i);
            s[32 + i] = fmaf(wi, s[32 + i], ki * vj);
        }
    }
    size_t sb = (size_t)bh * 65536 + (size_t)c * 4096;
#pragma unroll
    for (int i = 0; i < 64; ++i) g_xmix[sb + i * 64 + j] = s[i];
    // both halves write identical values; benign
    g_t1[bh * 1024 + c * 64 + lane]      = pw0;
    g_t1[bh * 1024 + c * 64 + lane + 32] = pw1;
}

// Combine: sequential scan over chunks (tiny): S0[c] = scan of (prodW, S).
__global__ void wkv_combine() {
    int tid = blockIdx.x * 256 + threadIdx.x;       // 262144 = 64*64*64
    int bh = tid >> 12;
    int i  = (tid >> 6) & 63;
    int j  = tid & 63;
    size_t sb = (size_t)bh * 65536 + i * 64 + j;
    float s0 = 0.f;
#pragma unroll
    for (int c = 0; c < NC; ++c) {
        g_sx[sb + (size_t)c * 4096] = s0;
        float pw = g_t1[bh * 1024 + c * 64 + i];
        s0 = fmaf(pw, s0, g_xmix[sb + (size_t)c * 4096]);
    }
}

// Pass B: replay chunk from true initial state, emit y/8 into g_og.
__global__ void __launch_bounds__(256)
wkv_passB(const float* __restrict__ u) {
    int wid  = blockIdx.x * 8 + (threadIdx.x >> 5);
    int lane = threadIdx.x & 31;
    int half = wid & 1, c = (wid >> 1) & (NC - 1), bh = wid >> 5;
    int b = bh >> 4, h = bh & 15;
    int j = half * 32 + lane;
    size_t base = (size_t)b * 1048576 + h * 64;
    float s[64];
    size_t sb = (size_t)bh * 65536 + (size_t)c * 4096;
#pragma unroll
    for (int i = 0; i < 64; ++i) s[i] = g_sx[sb + i * 64 + j];
    float u0 = u[h * 64 + lane], u1 = u[h * 64 + lane + 32];
    int t0 = c * CL;
    for (int t = 0; t < CL; ++t) {
        size_t off = base + (size_t)(t0 + t) * 1024;
        float k0 = g_kk[off + lane], k1 = g_kk[off + lane + 32];
        float w0 = g_wd[off + lane], w1 = g_wd[off + lane + 32];
        float r0 = g_rr[off + lane], r1 = g_rr[off + lane + 32];
        float vj = g_vv[off + j];
        // ct = sum_i r_i * u_i * k_i  (column-independent)
        float ct = fmaf(r0 * u0, k0, r1 * u1 * k1);
#pragma unroll
        for (int o = 16; o; o >>= 1) ct += __shfl_xor_sync(0xffffffffu, ct, o);
        float y = 0.f;
#pragma unroll
        for (int i = 0; i < 32; ++i) {
            float ri = __shfl_sync(0xffffffffu, r0, i);
            float ki = __shfl_sync(0xffffffffu, k0, i);
            float wi = __shfl_sync(0xffffffffu, w0, i);
            y = fmaf(ri, s[i], y);
            s[i] = fmaf(wi, s[i], ki * vj);
        }
#pragma unroll
        for (int i = 0; i < 32; ++i) {
            float ri = __shfl_sync(0xffffffffu, r1, i);
            float ki = __shfl_sync(0xffffffffu, k1, i);
            float wi = __shfl_sync(0xffffffffu, w1, i);
            y = fmaf(ri, s[32 + i], y);
            s[32 + i] = fmaf(wi, s[32 + i], ki * vj);
        }
        y = fmaf(vj, ct, y);
        g_og[off + j] = y * 0.125f;
    }
}

// GroupNorm (per head) + gate, in-place on g_og.
__global__ void __launch_bounds__(256)
gn_kernel(const float* __restrict__ lnw, const float* __restrict__ lnb) {
    int warp = blockIdx.x * 8 + (threadIdx.x >> 5);   // 0..65535 = 4096 rows * 16 heads
    int lane = threadIdx.x & 31;
    int row = warp >> 4, h = warp & 15;
    size_t off = (size_t)row * 1024 + h * 64;
    float y0 = g_og[off + lane], y1 = g_og[off + lane + 32];
    float sm = y0 + y1, sq = y0 * y0 + y1 * y1;
#pragma unroll
    for (int o = 16; o; o >>= 1) {
        sm += __shfl_xor_sync(0xffffffffu, sm, o);
        sq += __shfl_xor_sync(0xffffffffu, sq, o);
    }
    float mu  = sm * (1.f / 64.f);
    float var = sq * (1.f / 64.f) - mu * mu;
    float inv = rsqrtf(var + 1e-5f);
    float o0 = (y0 - mu) * inv * lnw[h * 64 + lane]      + lnb[h * 64 + lane];
    float o1 = (y1 - mu) * inv * lnw[h * 64 + lane + 32] + lnb[h * 64 + lane + 32];
    g_og[off + lane]      = o0 * g_gg[off + lane];
    g_og[off + lane + 32] = o1 * g_gg[off + lane + 32];
}

// ---------------- launch ----------------
extern "C" void kernel_launch(void* const* d_in, const int* in_sizes, int n_in,
                              void* d_out, int out_size) {
    const float* x          = (const float*)d_in[0];
    const float* x_maa      = (const float*)d_in[1];
    const float* w_maa      = (const float*)d_in[2];
    const float* k_maa      = (const float*)d_in[3];
    const float* v_maa      = (const float*)d_in[4];
    const float* r_maa      = (const float*)d_in[5];
    const float* gm_maa     = (const float*)d_in[6];
    const float* tm_w1      = (const float*)d_in[7];
    const float* tm_w2      = (const float*)d_in[8];
    const float* td_w1      = (const float*)d_in[9];
    const float* td_w2      = (const float*)d_in[10];
    const float* time_decay = (const float*)d_in[11];
    const float* time_first = (const float*)d_in[12];
    const float* Wr         = (const float*)d_in[13];
    const float* Wk         = (const float*)d_in[14];
    const float* Wv         = (const float*)d_in[15];
    const float* Wg         = (const float*)d_in[16];
    const float* Wo         = (const float*)d_in[17];
    const float* ln_w       = (const float*)d_in[18];
    const float* ln_b       = (const float*)d_in[19];
    float* out = (float*)d_out;

    // 1) token shift + xmix
    prep_kernel<<<(MT * CC / 4 + 255) / 256, 256>>>(x, x_maa);

    // 2) P = tanh(xmix @ tm_w1)   [4096,160]
    gemm_generic<1><<<dim3(3, 64), 256>>>(1, tm_w1, 2, MT, 160, CC);

    // 3) five mixed inputs wx/kx/vx/rx/gx (K=32 GEMM fused with apply)
    mix_kernel<<<dim3(8, 32, 5), 256>>>(x, w_maa, k_maa, v_maa, r_maa, gm_maa, tm_w2);

    // 4) batched projections r/k/v/g (silu fused into g)
    proj4_kernel<<<dim3(8, 32, 4), 256>>>(Wr, Wk, Wv, Wg);

    // 5) decay path: t1 = tanh(wx @ td_w1); wd = exp(-exp(td + t1 @ td_w2))
    gemm_generic<1><<<dim3(1, 64), 256>>>(3, td_w1, 12, MT, 64, CC);
    sgemm128<3><<<dim3(8, 32), 256>>>(12, td_w2, nullptr, 13, MT, CC, 64, time_decay);

    // 6) WKV chunked scan
    wkv_passA<<<256, 256>>>();
    wkv_combine<<<1024, 256>>>();
    wkv_passB<<<256, 256>>>(time_first);
    gn_kernel<<<8192, 256>>>(ln_w, ln_b);

    // 7) output projection
    sgemm128<0><<<dim3(8, 32), 256>>>(14, Wo, out, -1, MT, CC, CC, nullptr);
}

// round 4
// speedup vs baseline: 3.9922x; 2.1856x over previous
#include <cuda_runtime.h>
#include <cuda_bf16.h>
#include <math.h>
#include <stdint.h>

#define MT 4096      // B*T
#define CC 1024      // C
#define NH 16
#define HD 64
#define NC 16        // WKV chunks
#define CL 64        // chunk length (NC*CL = 1024 = T)

// ---------------- scratch (static device arrays; no allocations) ----------------
__device__ float g_sx  [MT*CC];   // sx; later reused as S0 (chunk initial states)
__device__ float g_xmix[MT*CC];   // xmix; later reused as S (chunk local end states)
__device__ float g_P   [MT*160];
__device__ float g_wx  [MT*CC];
__device__ float g_kx  [MT*CC];
__device__ float g_vx  [MT*CC];
__device__ float g_rx  [MT*CC];
__device__ float g_gx  [MT*CC];
__device__ float g_rr  [MT*CC];
__device__ float g_kk  [MT*CC];
__device__ float g_vv  [MT*CC];
__device__ float g_gg  [MT*CC];
__device__ float g_t1  [MT*64];   // t1; later reused as prodW
__device__ float g_wd  [MT*CC];
__device__ float g_og  [MT*CC];

__device__ __forceinline__ float* dbuf(int id) {
    switch (id) {
        case 0:  return g_sx;
        case 1:  return g_xmix;
        case 2:  return g_P;
        case 3:  return g_wx;
        case 4:  return g_kx;
        case 5:  return g_vx;
        case 6:  return g_rx;
        case 7:  return g_gx;
        case 8:  return g_rr;
        case 9:  return g_kk;
        case 10: return g_vv;
        case 11: return g_gg;
        case 12: return g_t1;
        case 13: return g_wd;
        default: return g_og;  // 14
    }
}

// ---------------- prep: sx = x_{t-1} - x_t ; xmix = x + sx*x_maa ----------------
__global__ void prep_kernel(const float* __restrict__ x, const float* __restrict__ x_maa) {
    int idx = (blockIdx.x * 256 + threadIdx.x) * 4;
    if (idx >= MT * CC) return;
    int row = idx / CC;
    int col = idx % CC;
    int t = row & 1023;
    float4 xc = *(const float4*)(x + idx);
    float4 xp;
    if (t == 0) xp = make_float4(0.f, 0.f, 0.f, 0.f);
    else        xp = *(const float4*)(x + idx - CC);
    float4 ma = *(const float4*)(x_maa + col);
    float4 s, m;
    s.x = xp.x - xc.x; s.y = xp.y - xc.y; s.z = xp.z - xc.z; s.w = xp.w - xc.w;
    m.x = fmaf(s.x, ma.x, xc.x); m.y = fmaf(s.y, ma.y, xc.y);
    m.z = fmaf(s.z, ma.z, xc.z); m.w = fmaf(s.w, ma.w, xc.w);
    *(float4*)(g_sx + idx)   = s;
    *(float4*)(g_xmix + idx) = m;
}

// ================= tf32 tensor-core GEMM (m16n8k8 mma.sync) =================
__device__ __forceinline__ uint32_t f2tf32(float f) {
    uint32_t u;
    asm("cvt.rna.tf32.f32 %0, %1;" : "=r"(u) : "f"(f));
    return u;
}

__device__ __forceinline__ void mma_tf32(float* c, const uint32_t* a, const uint32_t* b) {
    asm volatile(
        "mma.sync.aligned.m16n8k8.row.col.f32.tf32.tf32.f32 "
        "{%0,%1,%2,%3}, {%4,%5,%6,%7}, {%8,%9}, {%0,%1,%2,%3};\n"
        : "+f"(c[0]), "+f"(c[1]), "+f"(c[2]), "+f"(c[3])
        : "r"(a[0]), "r"(a[1]), "r"(a[2]), "r"(a[3]), "r"(b[0]), "r"(b[1]));
}

// Body: C[128x128 tile] = A[Mx K] @ B[K x N], tf32 inputs, fp32 accum.
// epi: 0=none 1=tanh 2=silu.  GUARD: N-dim guarding (N may be < bn+128).
// M rows and K are always full (M mult 128, K mult 16).
template<bool GUARD>
__device__ __forceinline__ void tf32_body(
    const float* __restrict__ A, const float* __restrict__ B, float* __restrict__ C,
    int N, int K, int epi)
{
    __shared__ float As[2][128][20];
    __shared__ float Bs[2][16][136];
    int tid = threadIdx.x;
    int bm = blockIdx.y * 128, bn = blockIdx.x * 128;
    int lane = tid & 31, wid = tid >> 5;
    int warp_m = (wid & 1) * 64, warp_n = (wid >> 1) * 32;
    int grp = lane >> 2, qid = lane & 3;

    // gmem staging mapping
    int ar = tid >> 2, ac = (tid & 3) * 4;     // A rows ar, ar+64 ; cols ac..ac+3
    int br = tid >> 5, bc = (tid & 31) * 4;    // B rows br, br+8  ; cols bc..bc+3
    const float* Ap = A + (size_t)(bm + ar) * K + ac;
    const float* Bp = B + (size_t)br * N + bn + bc;
    bool bin = !GUARD || (bn + bc < N);

    float4 av0, av1, bv0, bv1;
    av0 = *(const float4*)Ap;
    av1 = *(const float4*)(Ap + (size_t)64 * K);
    if (bin) { bv0 = *(const float4*)Bp; bv1 = *(const float4*)(Bp + (size_t)8 * N); }
    else     { bv0 = make_float4(0,0,0,0); bv1 = bv0; }

    // store buf 0 (tf32-converted)
    {
        As[0][ar][ac+0] = __uint_as_float(f2tf32(av0.x));
        As[0][ar][ac+1] = __uint_as_float(f2tf32(av0.y));
        As[0][ar][ac+2] = __uint_as_float(f2tf32(av0.z));
        As[0][ar][ac+3] = __uint_as_float(f2tf32(av0.w));
        As[0][ar+64][ac+0] = __uint_as_float(f2tf32(av1.x));
        As[0][ar+64][ac+1] = __uint_as_float(f2tf32(av1.y));
        As[0][ar+64][ac+2] = __uint_as_float(f2tf32(av1.z));
        As[0][ar+64][ac+3] = __uint_as_float(f2tf32(av1.w));
        float4 t0, t1;
        t0.x = __uint_as_float(f2tf32(bv0.x)); t0.y = __uint_as_float(f2tf32(bv0.y));
        t0.z = __uint_as_float(f2tf32(bv0.z)); t0.w = __uint_as_float(f2tf32(bv0.w));
        t1.x = __uint_as_float(f2tf32(bv1.x)); t1.y = __uint_as_float(f2tf32(bv1.y));
        t1.z = __uint_as_float(f2tf32(bv1.z)); t1.w = __uint_as_float(f2tf32(bv1.w));
        *(float4*)&Bs[0][br][bc]   = t0;
        *(float4*)&Bs[0][br+8][bc] = t1;
    }
    __syncthreads();

    float acc[16][4];
#pragma unroll
    for (int i = 0; i < 16; ++i)
#pragma unroll
        for (int q = 0; q < 4; ++q) acc[i][q] = 0.f;

    int nk = K >> 4;
    for (int kt = 0; kt < nk; ++kt) {
        int cur = kt & 1;
        bool more = (kt + 1 < nk);
        if (more) {
            const float* Ap2 = Ap + (kt + 1) * 16;
            const float* Bp2 = Bp + (size_t)(kt + 1) * 16 * N;
            av0 = *(const float4*)Ap2;
            av1 = *(const float4*)(Ap2 + (size_t)64 * K);
            if (bin) { bv0 = *(const float4*)Bp2; bv1 = *(const float4*)(Bp2 + (size_t)8 * N); }
        }
#pragma unroll
        for (int kk = 0; kk < 16; kk += 8) {
            uint32_t af[4][4], bf[4][2];
#pragma unroll
            for (int mt = 0; mt < 4; ++mt) {
                int r0 = warp_m + mt * 16 + grp;
                af[mt][0] = __float_as_uint(As[cur][r0][kk + qid]);
                af[mt][1] = __float_as_uint(As[cur][r0 + 8][kk + qid]);
                af[mt][2] = __float_as_uint(As[cur][r0][kk + qid + 4]);
                af[mt][3] = __float_as_uint(As[cur][r0 + 8][kk + qid + 4]);
            }
#pragma unroll
            for (int nt = 0; nt < 4; ++nt) {
                int c0 = warp_n + nt * 8 + grp;
                bf[nt][0] = __float_as_uint(Bs[cur][kk + qid][c0]);
                bf[nt][1] = __float_as_uint(Bs[cur][kk + qid + 4][c0]);
            }
#pragma unroll
            for (int mt = 0; mt < 4; ++mt)
#pragma unroll
                for (int nt = 0; nt < 4; ++nt)
                    mma_tf32(acc[mt * 4 + nt], af[mt], bf[nt]);
        }
        if (more) {
            int nxt = cur ^ 1;
            As[nxt][ar][ac+0] = __uint_as_float(f2tf32(av0.x));
            As[nxt][ar][ac+1] = __uint_as_float(f2tf32(av0.y));
            As[nxt][ar][ac+2] = __uint_as_float(f2tf32(av0.z));
            As[nxt][ar][ac+3] = __uint_as_float(f2tf32(av0.w));
            As[nxt][ar+64][ac+0] = __uint_as_float(f2tf32(av1.x));
            As[nxt][ar+64][ac+1] = __uint_as_float(f2tf32(av1.y));
            As[nxt][ar+64][ac+2] = __uint_as_float(f2tf32(av1.z));
            As[nxt][ar+64][ac+3] = __uint_as_float(f2tf32(av1.w));
            float4 t0, t1;
            if (!bin) { bv0 = make_float4(0,0,0,0); bv1 = bv0; }
            t0.x = __uint_as_float(f2tf32(bv0.x)); t0.y = __uint_as_float(f2tf32(bv0.y));
            t0.z = __uint_as_float(f2tf32(bv0.z)); t0.w = __uint_as_float(f2tf32(bv0.w));
            t1.x = __uint_as_float(f2tf32(bv1.x)); t1.y = __uint_as_float(f2tf32(bv1.y));
            t1.z = __uint_as_float(f2tf32(bv1.z)); t1.w = __uint_as_float(f2tf32(bv1.w));
            *(float4*)&Bs[nxt][br][bc]   = t0;
            *(float4*)&Bs[nxt][br+8][bc] = t1;
            __syncthreads();
        }
    }

    // epilogue
#pragma unroll
    for (int mt = 0; mt < 4; ++mt) {
#pragma unroll
        for (int nt = 0; nt < 4; ++nt) {
            const float* a = acc[mt * 4 + nt];
            int gr = bm + warp_m + mt * 16 + grp;
            int gc = bn + warp_n + nt * 8 + qid * 2;
            if (GUARD && gc >= N) continue;
            float v[4] = { a[0], a[1], a[2], a[3] };
            if (epi == 1) {
#pragma unroll
                for (int q = 0; q < 4; ++q) v[q] = tanhf(v[q]);
            } else if (epi == 2) {
#pragma unroll
                for (int q = 0; q < 4; ++q) {
                    float sg = 1.f / (1.f + expf(-v[q]));
                    v[q] = v[q] * sg;
                }
            }
            float2 p0 = make_float2(v[0], v[1]);
            float2 p1 = make_float2(v[2], v[3]);
            *(float2*)(C + (size_t)gr * N + gc)       = p0;
            *(float2*)(C + (size_t)(gr + 8) * N + gc) = p1;
        }
    }
}

// 4-way batched projections r/k/v/g (silu on g)
__global__ void __launch_bounds__(256)
tf32_proj4(const float* __restrict__ Wr, const float* __restrict__ Wk,
           const float* __restrict__ Wv, const float* __restrict__ Wg) {
    int z = blockIdx.z;
    const float* A = (z == 0) ? g_rx : (z == 1) ? g_kx : (z == 2) ? g_vx : g_gx;
    const float* B = (z == 0) ? Wr : (z == 1) ? Wk : (z == 2) ? Wv : Wg;
    float* C       = (z == 0) ? g_rr : (z == 1) ? g_kk : (z == 2) ? g_vv : g_gg;
    tf32_body<false>(A, B, C, CC, CC, (z == 3) ? 2 : 0);
}

template<bool GUARD>
__global__ void __launch_bounds__(256)
tf32_gemm(int a_id, const float* __restrict__ Bw, float* __restrict__ Cext, int c_id,
          int N, int K, int epi) {
    const float* A = dbuf(a_id);
    float* C = (c_id < 0) ? Cext : dbuf(c_id);
    tf32_body<GUARD>(A, Bw, C, N, K, epi);
}

// ---------------- fp32 128x128x8 double-buffered SGEMM (decay path only) ----------------
// EPI 3: exp(-exp(extra[col]+v))
__global__ void __launch_bounds__(256)
sgemm128_wd(const float* __restrict__ B, const float* __restrict__ extra) {
    const float* A = g_t1;    // [4096, 64]
    float* C = g_wd;
    const int N = CC, K = 64;
    __shared__ float As[2][8][128];
    __shared__ float Bs[2][8][128];
    int tid = threadIdx.x;
    int bm = blockIdx.y * 128, bn = blockIdx.x * 128;
    int arow = tid >> 1,  acol = (tid & 1) * 4;
    int brow = tid >> 5,  bcol = (tid & 31) * 4;
    const float* Ap = A + (size_t)(bm + arow) * K + acol;
    const float* Bp = B + (size_t)brow * N + bn + bcol;
    int tx = (tid & 15) * 8, ty = (tid >> 4) * 8;
    float acc[8][8] = {};

    float4 a4 = *(const float4*)Ap;
    float4 b4 = *(const float4*)Bp;
    As[0][acol + 0][arow] = a4.x; As[0][acol + 1][arow] = a4.y;
    As[0][acol + 2][arow] = a4.z; As[0][acol + 3][arow] = a4.w;
    *(float4*)&Bs[0][brow][bcol] = b4;
    __syncthreads();

    const int nk = K >> 3;
    for (int kt = 0; kt < nk; ++kt) {
        int cur = kt & 1;
        bool more = (kt + 1 < nk);
        float4 a4n, b4n;
        if (more) {
            a4n = *(const float4*)(Ap + (size_t)(kt + 1) * 8);
            b4n = *(const float4*)(Bp + (size_t)(kt + 1) * 8 * N);
        }
#pragma unroll
        for (int kk = 0; kk < 8; ++kk) {
            float ra[8], rb[8];
#pragma unroll
            for (int i = 0; i < 8; ++i) { ra[i] = As[cur][kk][ty + i]; rb[i] = Bs[cur][kk][tx + i]; }
#pragma unroll
            for (int i = 0; i < 8; ++i)
#pragma unroll
                for (int j = 0; j < 8; ++j)
                    acc[i][j] = fmaf(ra[i], rb[j], acc[i][j]);
        }
        if (more) {
            int nxt = cur ^ 1;
            As[nxt][acol + 0][arow] = a4n.x; As[nxt][acol + 1][arow] = a4n.y;
            As[nxt][acol + 2][arow] = a4n.z; As[nxt][acol + 3][arow] = a4n.w;
            *(float4*)&Bs[nxt][brow][bcol] = b4n;
            __syncthreads();
        }
    }

#pragma unroll
    for (int i = 0; i < 8; ++i) {
        size_t rowoff = (size_t)(bm + ty + i) * N;
#pragma unroll
        for (int j = 0; j < 8; j += 4) {
            float4 v;
            v.x = expf(-expf(extra[bn + tx + j + 0] + acc[i][j]));
            v.y = expf(-expf(extra[bn + tx + j + 1] + acc[i][j + 1]));
            v.z = expf(-expf(extra[bn + tx + j + 2] + acc[i][j + 2]));
            v.w = expf(-expf(extra[bn + tx + j + 3] + acc[i][j + 3]));
            *(float4*)(C + rowoff + bn + tx + j) = v;
        }
    }
}

// ---------------- fused K=32 mix GEMM + apply: out = x + sx*(maa + P_f @ W2_f) ----------------
__global__ void __launch_bounds__(256)
mix_kernel(const float* __restrict__ x,
           const float* __restrict__ w_maa, const float* __restrict__ k_maa,
           const float* __restrict__ v_maa, const float* __restrict__ r_maa,
           const float* __restrict__ gm_maa,
           const float* __restrict__ tm_w2) {
    int f = blockIdx.z;
    int bm = blockIdx.y * 128, bn = blockIdx.x * 128;
    __shared__ float Ps[128][33];
    __shared__ float Ws[32][128];
    int tid = threadIdx.x;
    for (int i = tid; i < 128 * 8; i += 256) {
        int r = i >> 3, c4 = (i & 7) * 4;
        float4 p4 = *(const float4*)(g_P + (size_t)(bm + r) * 160 + f * 32 + c4);
        Ps[r][c4] = p4.x; Ps[r][c4 + 1] = p4.y; Ps[r][c4 + 2] = p4.z; Ps[r][c4 + 3] = p4.w;
    }
    for (int i = tid; i < 32 * 32; i += 256) {
        int r = i >> 5, c4 = (i & 31) * 4;
        *(float4*)&Ws[r][c4] = *(const float4*)(tm_w2 + ((size_t)f * 32 + r) * 1024 + bn + c4);
    }
    __syncthreads();
    int tx = (tid & 15) * 8, ty = (tid >> 4) * 8;
    float acc[8][8] = {};
#pragma unroll
    for (int kk = 0; kk < 32; ++kk) {
        float ra[8], rb[8];
#pragma unroll
        for (int i = 0; i < 8; ++i) { ra[i] = Ps[ty + i][kk]; rb[i] = Ws[kk][tx + i]; }
#pragma unroll
        for (int i = 0; i < 8; ++i)
#pragma unroll
            for (int j = 0; j < 8; ++j)
                acc[i][j] = fmaf(ra[i], rb[j], acc[i][j]);
    }
    const float* maa = (f == 0) ? w_maa : (f == 1) ? k_maa : (f == 2) ? v_maa : (f == 3) ? r_maa : gm_maa;
    float* out = (f == 0) ? g_wx : (f == 1) ? g_kx : (f == 2) ? g_vx : (f == 3) ? g_rx : g_gx;
#pragma unroll
    for (int i = 0; i < 8; ++i) {
        size_t rowoff = (size_t)(bm + ty + i) * 1024;
#pragma unroll
        for (int j = 0; j < 8; ++j) {
            int gc = bn + tx + j;
            float m = acc[i][j];
            out[rowoff + gc] = fmaf(g_sx[rowoff + gc], maa[gc] + m, x[rowoff + gc]);
        }
    }
}

// ================= WKV: chunked parallel scan, barrier-free warps =================
__global__ void __launch_bounds__(256)
wkv_passA() {
    int wid  = blockIdx.x * 8 + (threadIdx.x >> 5);
    int lane = threadIdx.x & 31;
    int half = wid & 1, c = (wid >> 1) & (NC - 1), bh = wid >> 5;
    int b = bh >> 4, h = bh & 15;
    int j = half * 32 + lane;
    size_t base = (size_t)b * 1048576 + h * 64;
    float s[64];
#pragma unroll
    for (int i = 0; i < 64; ++i) s[i] = 0.f;
    float pw0 = 1.f, pw1 = 1.f;
    int t0 = c * CL;
    for (int t = 0; t < CL; ++t) {
        size_t off = base + (size_t)(t0 + t) * 1024;
        float k0 = g_kk[off + lane], k1 = g_kk[off + lane + 32];
        float w0 = g_wd[off + lane], w1 = g_wd[off + lane + 32];
        float vj = g_vv[off + j];
        pw0 *= w0; pw1 *= w1;
#pragma unroll
        for (int i = 0; i < 32; ++i) {
            float ki = __shfl_sync(0xffffffffu, k0, i);
            float wi = __shfl_sync(0xffffffffu, w0, i);
            s[i] = fmaf(wi, s[i], ki * vj);
        }
#pragma unroll
        for (int i = 0; i < 32; ++i) {
            float ki = __shfl_sync(0xffffffffu, k1, i);
            float wi = __shfl_sync(0xffffffffu, w1, i);
            s[32 + i] = fmaf(wi, s[32 + i], ki * vj);
        }
    }
    size_t sb = (size_t)bh * 65536 + (size_t)c * 4096;
#pragma unroll
    for (int i = 0; i < 64; ++i) g_xmix[sb + i * 64 + j] = s[i];
    g_t1[bh * 1024 + c * 64 + lane]      = pw0;
    g_t1[bh * 1024 + c * 64 + lane + 32] = pw1;
}

__global__ void wkv_combine() {
    int tid = blockIdx.x * 256 + threadIdx.x;       // 262144 = 64*64*64
    int bh = tid >> 12;
    int i  = (tid >> 6) & 63;
    int j  = tid & 63;
    size_t sb = (size_t)bh * 65536 + i * 64 + j;
    float s0 = 0.f;
#pragma unroll
    for (int c = 0; c < NC; ++c) {
        g_sx[sb + (size_t)c * 4096] = s0;
        float pw = g_t1[bh * 1024 + c * 64 + i];
        s0 = fmaf(pw, s0, g_xmix[sb + (size_t)c * 4096]);
    }
}

__global__ void __launch_bounds__(256)
wkv_passB(const float* __restrict__ u) {
    int wid  = blockIdx.x * 8 + (threadIdx.x >> 5);
    int lane = threadIdx.x & 31;
    int half = wid & 1, c = (wid >> 1) & (NC - 1), bh = wid >> 5;
    int b = bh >> 4, h = bh & 15;
    int j = half * 32 + lane;
    size_t base = (size_t)b * 1048576 + h * 64;
    float s[64];
    size_t sb = (size_t)bh * 65536 + (size_t)c * 4096;
#pragma unroll
    for (int i = 0; i < 64; ++i) s[i] = g_sx[sb + i * 64 + j];
    float u0 = u[h * 64 + lane], u1 = u[h * 64 + lane + 32];
    int t0 = c * CL;
    for (int t = 0; t < CL; ++t) {
        size_t off = base + (size_t)(t0 + t) * 1024;
        float k0 = g_kk[off + lane], k1 = g_kk[off + lane + 32];
        float w0 = g_wd[off + lane], w1 = g_wd[off + lane + 32];
        float r0 = g_rr[off + lane], r1 = g_rr[off + lane + 32];
        float vj = g_vv[off + j];
        float ct = fmaf(r0 * u0, k0, r1 * u1 * k1);
#pragma unroll
        for (int o = 16; o; o >>= 1) ct += __shfl_xor_sync(0xffffffffu, ct, o);
        float y = 0.f;
#pragma unroll
        for (int i = 0; i < 32; ++i) {
            float ri = __shfl_sync(0xffffffffu, r0, i);
            float ki = __shfl_sync(0xffffffffu, k0, i);
            float wi = __shfl_sync(0xffffffffu, w0, i);
            y = fmaf(ri, s[i], y);
            s[i] = fmaf(wi, s[i], ki * vj);
        }
#pragma unroll
        for (int i = 0; i < 32; ++i) {
            float ri = __shfl_sync(0xffffffffu, r1, i);
            float ki = __shfl_sync(0xffffffffu, k1, i);
            float wi = __shfl_sync(0xffffffffu, w1, i);
            y = fmaf(ri, s[32 + i], y);
            s[32 + i] = fmaf(wi, s[32 + i], ki * vj);
        }
        y = fmaf(vj, ct, y);
        g_og[off + j] = y * 0.125f;
    }
}

__global__ void __launch_bounds__(256)
gn_kernel(const float* __restrict__ lnw, const float* __restrict__ lnb) {
    int warp = blockIdx.x * 8 + (threadIdx.x >> 5);
    int lane = threadIdx.x & 31;
    int row = warp >> 4, h = warp & 15;
    size_t off = (size_t)row * 1024 + h * 64;
    float y0 = g_og[off + lane], y1 = g_og[off + lane + 32];
    float sm = y0 + y1, sq = y0 * y0 + y1 * y1;
#pragma unroll
    for (int o = 16; o; o >>= 1) {
        sm += __shfl_xor_sync(0xffffffffu, sm, o);
        sq += __shfl_xor_sync(0xffffffffu, sq, o);
    }
    float mu  = sm * (1.f / 64.f);
    float var = sq * (1.f / 64.f) - mu * mu;
    float inv = rsqrtf(var + 1e-5f);
    float o0 = (y0 - mu) * inv * lnw[h * 64 + lane]      + lnb[h * 64 + lane];
    float o1 = (y1 - mu) * inv * lnw[h * 64 + lane + 32] + lnb[h * 64 + lane + 32];
    g_og[off + lane]      = o0 * g_gg[off + lane];
    g_og[off + lane + 32] = o1 * g_gg[off + lane + 32];
}

// ---------------- launch ----------------
extern "C" void kernel_launch(void* const* d_in, const int* in_sizes, int n_in,
                              void* d_out, int out_size) {
    const float* x          = (const float*)d_in[0];
    const float* x_maa      = (const float*)d_in[1];
    const float* w_maa      = (const float*)d_in[2];
    const float* k_maa      = (const float*)d_in[3];
    const float* v_maa      = (const float*)d_in[4];
    const float* r_maa      = (const float*)d_in[5];
    const float* gm_maa     = (const float*)d_in[6];
    const float* tm_w1      = (const float*)d_in[7];
    const float* tm_w2      = (const float*)d_in[8];
    const float* td_w1      = (const float*)d_in[9];
    const float* td_w2      = (const float*)d_in[10];
    const float* time_decay = (const float*)d_in[11];
    const float* time_first = (const float*)d_in[12];
    const float* Wr         = (const float*)d_in[13];
    const float* Wk         = (const float*)d_in[14];
    const float* Wv         = (const float*)d_in[15];
    const float* Wg         = (const float*)d_in[16];
    const float* Wo         = (const float*)d_in[17];
    const float* ln_w       = (const float*)d_in[18];
    const float* ln_b       = (const float*)d_in[19];
    float* out = (float*)d_out;

    // 1) token shift + xmix
    prep_kernel<<<(MT * CC / 4 + 255) / 256, 256>>>(x, x_maa);

    // 2) P = tanh(xmix @ tm_w1)   [4096,160]  (tf32, guarded N)
    tf32_gemm<true><<<dim3(2, 32), 256>>>(1, tm_w1, nullptr, 2, 160, CC, 1);

    // 3) five mixed inputs wx/kx/vx/rx/gx (K=32 GEMM fused with apply)
    mix_kernel<<<dim3(8, 32, 5), 256>>>(x, w_maa, k_maa, v_maa, r_maa, gm_maa, tm_w2);

    // 4) batched projections r/k/v/g (tf32 tensor cores; silu fused into g)
    tf32_proj4<<<dim3(8, 32, 4), 256>>>(Wr, Wk, Wv, Wg);

    // 5) decay path: t1 = tanh(wx @ td_w1) (tf32 guarded); wd = exp(-exp(td + t1 @ td_w2)) (fp32)
    tf32_gemm<true><<<dim3(1, 32), 256>>>(3, td_w1, nullptr, 12, 64, CC, 1);
    sgemm128_wd<<<dim3(8, 32), 256>>>(td_w2, time_decay);

    // 6) WKV chunked scan
    wkv_passA<<<256, 256>>>();
    wkv_combine<<<1024, 256>>>();
    wkv_passB<<<256, 256>>>(time_first);
    gn_kernel<<<8192, 256>>>(ln_w, ln_b);

    // 7) output projection (tf32)
    tf32_gemm<false><<<dim3(8, 32), 256>>>(14, Wo, out, -1, CC, CC, 0);
}